// round 1
// baseline (speedup 1.0000x reference)
#include <cuda_runtime.h>
#include <cuda_bf16.h>
#include <cstdint>

// Problem constants
#define CORES   512
#define SLOTS   4
#define SLEN    64
#define PER_CORE (SLOTS * SLEN)          // 256
#define NSLOTS  (CORES * SLOTS)          // 2048 routing slots per layer
#define VEC_N   (CORES * PER_CORE)       // 131072 elements of h / y
#define C_ENTRIES (CORES * SLOTS * CORES * SLOTS)  // 4,194,304
#define LIST_CAP 8

// Device scratch (allocation-free rule: __device__ globals)
__device__ float g_h[VEC_N];     // dispatch result (reused for both layers)
__device__ float g_y1[VEC_N];    // layer-1 activated output
__device__ int   g_cnt[2 * NSLOTS];
__device__ int2  g_list[2 * NSLOTS * LIST_CAP];

// ---------------------------------------------------------------------------
// Zero the per-slot counters (4096 ints)
// ---------------------------------------------------------------------------
__global__ void zero_cnt_kernel(int* __restrict__ cnt) {
    int i = blockIdx.x * blockDim.x + threadIdx.x;
    if (i < 2 * NSLOTS) cnt[i] = 0;
}

// ---------------------------------------------------------------------------
// Compact dense routing tensor C [I,J,K,L] (i-major, l innermost) into
// per-(k,l)-slot lists of (src = i*4+j, weight). Each slot has <=4 nonzeros.
// One float4 covers all 4 l-values of a given (ij, k).
// ---------------------------------------------------------------------------
__global__ void compact_kernel(const float4* __restrict__ C4,
                               int* __restrict__ cnt,
                               int2* __restrict__ lst) {
    const int n4 = C_ENTRIES / 4;  // 1,048,576
    for (int q = blockIdx.x * blockDim.x + threadIdx.x; q < n4;
         q += gridDim.x * blockDim.x) {
        float4 v = C4[q];
        int ij = q >> 9;        // q = ij*512 + k
        int k  = q & 511;
        float vals[4] = {v.x, v.y, v.z, v.w};
#pragma unroll
        for (int l = 0; l < 4; l++) {
            if (vals[l] != 0.0f) {
                int s = k * 4 + l;
                int pos = atomicAdd(&cnt[s], 1);
                if (pos < LIST_CAP)
                    lst[s * LIST_CAP + pos] = make_int2(ij, __float_as_int(vals[l]));
            }
        }
    }
}

// ---------------------------------------------------------------------------
// Gather dispatch: h[s*64+m] = sum_e w_e * src[src_e*64 + m].
// Atomic-free, fully coalesced (32 consecutive m per warp-half).
// ---------------------------------------------------------------------------
__global__ void gather_kernel(const int* __restrict__ cnt,
                              const int2* __restrict__ lst,
                              const float* __restrict__ src,
                              float* __restrict__ h) {
    int idx = blockIdx.x * blockDim.x + threadIdx.x;  // 131072 threads
    int m = idx & (SLEN - 1);
    int s = idx >> 6;
    int n = cnt[s];
    if (n > LIST_CAP) n = LIST_CAP;
    float acc = 0.0f;
    for (int e = 0; e < n; e++) {
        int2 ent = lst[s * LIST_CAP + e];
        acc += __int_as_float(ent.y) * src[ent.x * SLEN + m];
    }
    h[idx] = acc;
}

// ---------------------------------------------------------------------------
// Batched per-core matvec + capped ReLU.
// W layout per core: [j,k,l,m] (j stride 16384, k stride 4096, l stride 64).
// Output row r = j*64+l, column c = k*64+m, h per-core element c = k*64+m.
// 1 CTA / core, 8 warps, warp owns 32 rows, 4-row unroll for MLP.
// ---------------------------------------------------------------------------
__global__ void __launch_bounds__(256) matvec_kernel(
        const float* __restrict__ W,
        const float* __restrict__ h,
        float* __restrict__ y) {
    __shared__ float4 hs[PER_CORE / 4];  // 64 float4 = 256 floats
    const int core = blockIdx.x;
    const float* Wc = W + (size_t)core * (PER_CORE * PER_CORE);
    const int tid = threadIdx.x;
    if (tid < 64) hs[tid] = reinterpret_cast<const float4*>(h + core * PER_CORE)[tid];
    __syncthreads();

    const int warp = tid >> 5, lane = tid & 31;
    // Lane's two float4 column positions: c0 = lane*4 in [0,128), c1 = c0+128
    const int c0 = lane * 4;
    const int c1 = c0 + 128;
    const float4 hv0 = hs[lane];
    const float4 hv1 = hs[32 + lane];
    const int off0 = (c0 >> 6) * 4096 + (c0 & 63);
    const int off1 = (c1 >> 6) * 4096 + (c1 & 63);

    for (int rr = 0; rr < 32; rr += 4) {
        float acc[4];
#pragma unroll
        for (int u = 0; u < 4; u++) {
            int r = warp * 32 + rr + u;
            int j = r >> 6, l = r & 63;
            const float* rb = Wc + j * 16384 + l * 64;
            float4 w0 = *reinterpret_cast<const float4*>(rb + off0);
            float4 w1 = *reinterpret_cast<const float4*>(rb + off1);
            acc[u] = w0.x * hv0.x + w0.y * hv0.y + w0.z * hv0.z + w0.w * hv0.w
                   + w1.x * hv1.x + w1.y * hv1.y + w1.z * hv1.z + w1.w * hv1.w;
        }
#pragma unroll
        for (int u = 0; u < 4; u++) {
#pragma unroll
            for (int o = 16; o > 0; o >>= 1)
                acc[u] += __shfl_xor_sync(0xffffffffu, acc[u], o);
        }
        if (lane == 0) {
#pragma unroll
            for (int u = 0; u < 4; u++) {
                int r = warp * 32 + rr + u;
                float v = fminf(fmaxf(acc[u], 0.0f), 10.0f);
                y[core * PER_CORE + r] = v;
                // note: r varies with u; recompute index properly below
            }
        }
    }
}

// ---------------------------------------------------------------------------
// Launch sequence (graph-capturable: kernels only)
// ---------------------------------------------------------------------------
extern "C" void kernel_launch(void* const* d_in, const int* in_sizes, int n_in,
                              void* d_out, int out_size) {
    const float* x  = (const float*)d_in[0];
    const float* Wi = (const float*)d_in[1];
    const float* Wo = (const float*)d_in[2];
    const float* Ci = (const float*)d_in[3];
    const float* Cc = (const float*)d_in[4];
    float* out = (float*)d_out;

    // Resolve scratch symbol addresses (host-side query, capture-safe)
    float* h;   cudaGetSymbolAddress((void**)&h,   g_h);
    float* y1;  cudaGetSymbolAddress((void**)&y1,  g_y1);
    int*   cnt; cudaGetSymbolAddress((void**)&cnt, g_cnt);
    int2*  lst; cudaGetSymbolAddress((void**)&lst, g_list);

    int* cnt1 = cnt;           int2* lst1 = lst;
    int* cnt2 = cnt + NSLOTS;  int2* lst2 = lst + NSLOTS * LIST_CAP;

    zero_cnt_kernel<<<(2 * NSLOTS + 255) / 256, 256>>>(cnt);

    compact_kernel<<<2048, 256>>>((const float4*)Ci, cnt1, lst1);
    compact_kernel<<<2048, 256>>>((const float4*)Cc, cnt2, lst2);

    // Layer 1
    gather_kernel<<<VEC_N / 256, 256>>>(cnt1, lst1, x, h);
    matvec_kernel<<<CORES, 256>>>(Wi, h, y1);

    // Layer 2
    gather_kernel<<<VEC_N / 256, 256>>>(cnt2, lst2, y1, h);
    matvec_kernel<<<CORES, 256>>>(Wo, h, out);
}

// round 3
// speedup vs baseline: 1.2166x; 1.2166x over previous
#include <cuda_runtime.h>
#include <cuda_bf16.h>
#include <cstdint>

#define CORES   512
#define SLOTS   4
#define SLEN    64
#define PER_CORE (SLOTS * SLEN)          // 256
#define NSLOTS  (CORES * SLOTS)          // 2048 slots per layer
#define VEC_N   (CORES * PER_CORE)       // 131072
#define C_ENTRIES (CORES * SLOTS * CORES * SLOTS)
#define LIST_CAP 8

// Scratch (__device__ globals; no allocation allowed)
__device__ float g_y1[VEC_N];
__device__ int   g_cnt[2 * NSLOTS];
__device__ int2  g_list[2 * NSLOTS * LIST_CAP];

// ---------------------------------------------------------------------------
__global__ void zero_cnt_kernel(int* __restrict__ cnt) {
    int i = blockIdx.x * blockDim.x + threadIdx.x;
    if (i < 2 * NSLOTS) cnt[i] = 0;
}

// ---------------------------------------------------------------------------
// Compact both routing tensors in one launch.
// C layout [I,J,K,L]: q = ij*512 + k indexes a float4 over l.
// ---------------------------------------------------------------------------
__global__ void compact_kernel(const float4* __restrict__ C1,
                               const float4* __restrict__ C2,
                               int* __restrict__ cnt,
                               int2* __restrict__ lst) {
    const int n4 = C_ENTRIES / 4;           // per tensor
    int g = blockIdx.x * blockDim.x + threadIdx.x;
    int half = gridDim.x * blockDim.x / 2;
    const float4* C = (g < half) ? C1 : C2;
    int* cn  = (g < half) ? cnt : cnt + NSLOTS;
    int2* ls = (g < half) ? lst : lst + NSLOTS * LIST_CAP;
    int base = (g < half) ? g : g - half;
    int stride = half;
    for (int q = base; q < n4; q += stride) {
        float4 v = __ldcs(&C[q]);
        int ij = q >> 9;
        int k  = q & 511;
        float vals[4] = {v.x, v.y, v.z, v.w};
#pragma unroll
        for (int l = 0; l < 4; l++) {
            if (vals[l] != 0.0f) {
                int s = k * 4 + l;
                int pos = atomicAdd(&cn[s], 1);
                if (pos < LIST_CAP)
                    ls[s * LIST_CAP + pos] = make_int2(ij, __float_as_int(vals[l]));
            }
        }
    }
}

// ---------------------------------------------------------------------------
// Fused dispatch-gather + per-core matvec + capped ReLU.
// Prologue: 256 threads each build one h element of this core from its
// (slot, weight) list (list loads broadcast, src loads coalesced).
// Main: warp covers 32 rows; within a row-group of 4, lanes split as
// (sub = lane>>3 -> row, lg = lane&7 -> 128B column chunk). 8 independent
// LDG.128 per row-group, 3-level shfl reduction within 8-lane groups.
// W per-core layout [j,k,l,m]: row r=(j,l) stride j:16384 l:64; col c=(k,m).
// ---------------------------------------------------------------------------
__global__ void __launch_bounds__(256) fused_mv_kernel(
        const float* __restrict__ W,
        const int*  __restrict__ cnt,
        const int2* __restrict__ lst,
        const float* __restrict__ src,
        float* __restrict__ y) {
    __shared__ float hs[PER_CORE];
    const int core = blockIdx.x;
    const int tid  = threadIdx.x;

    // --- gather h for this core ---
    {
        int s = core * SLOTS + (tid >> 6);
        int m = tid & 63;
        int n = cnt[s];
        if (n > LIST_CAP) n = LIST_CAP;
        float acc = 0.0f;
#pragma unroll 4
        for (int e = 0; e < n; e++) {
            int2 ent = lst[s * LIST_CAP + e];
            acc += __int_as_float(ent.y) * src[ent.x * SLEN + m];
        }
        hs[tid] = acc;
    }
    __syncthreads();

    const int warp = tid >> 5, lane = tid & 31;
    const int lg  = lane & 7;    // column-chunk index
    const int sub = lane >> 3;   // row within group of 4

    // Preload this lane's 8 h-chunks (float4 each) into registers
    float4 hv[8];
#pragma unroll
    for (int t = 0; t < 8; t++)
        hv[t] = reinterpret_cast<const float4*>(hs)[lg + 8 * t];

    const float* Wc = W + (size_t)core * (PER_CORE * PER_CORE);

#pragma unroll 2
    for (int rg = 0; rg < 8; rg++) {
        int r = warp * 32 + rg * 4 + sub;
        int j = r >> 6, l = r & 63;
        const float* rb = Wc + j * 16384 + l * 64;
        float acc = 0.0f;
#pragma unroll
        for (int t = 0; t < 8; t++) {
            int c = 4 * lg + 32 * t;
            float4 w = __ldcs(reinterpret_cast<const float4*>(
                                  rb + (c >> 6) * 4096 + (c & 63)));
            acc += w.x * hv[t].x + w.y * hv[t].y + w.z * hv[t].z + w.w * hv[t].w;
        }
        acc += __shfl_xor_sync(0xffffffffu, acc, 1);
        acc += __shfl_xor_sync(0xffffffffu, acc, 2);
        acc += __shfl_xor_sync(0xffffffffu, acc, 4);
        if (lg == 0)
            y[core * PER_CORE + r] = fminf(fmaxf(acc, 0.0f), 10.0f);
    }
}

// ---------------------------------------------------------------------------
extern "C" void kernel_launch(void* const* d_in, const int* in_sizes, int n_in,
                              void* d_out, int out_size) {
    const float* x  = (const float*)d_in[0];
    const float* Wi = (const float*)d_in[1];
    const float* Wo = (const float*)d_in[2];
    const float* Ci = (const float*)d_in[3];
    const float* Cc = (const float*)d_in[4];
    float* out = (float*)d_out;

    float* y1;  cudaGetSymbolAddress((void**)&y1,  g_y1);
    int*   cnt; cudaGetSymbolAddress((void**)&cnt, g_cnt);
    int2*  lst; cudaGetSymbolAddress((void**)&lst, g_list);

    zero_cnt_kernel<<<(2 * NSLOTS + 255) / 256, 256>>>(cnt);

    compact_kernel<<<4096, 256>>>((const float4*)Ci, (const float4*)Cc,
                                  cnt, lst);

    // Layer 1: dispatch(x)+matvec(Wi) -> y1
    fused_mv_kernel<<<CORES, 256>>>(Wi, cnt, lst, x, y1);

    // Layer 2: dispatch(y1)+matvec(Wo) -> out
    fused_mv_kernel<<<CORES, 256>>>(Wo, cnt + NSLOTS,
                                    lst + NSLOTS * LIST_CAP, y1, out);
}

// round 4
// speedup vs baseline: 1.2560x; 1.0324x over previous
#include <cuda_runtime.h>
#include <cuda_bf16.h>
#include <cstdint>

#define CORES   512
#define SLOTS   4
#define SLEN    64
#define PER_CORE (SLOTS * SLEN)          // 256
#define NSLOTS  (CORES * SLOTS)          // 2048 slots per layer
#define VEC_N   (CORES * PER_CORE)       // 131072
#define C_ENTRIES (CORES * SLOTS * CORES * SLOTS)
#define LIST_CAP 8
#define NTASKS  (CORES * 2)              // half-core tasks
#define GRID_MV 592                      // 148 SMs x 4 CTAs (one full wave)

// Scratch (__device__ globals; no allocation allowed)
__device__ float g_y1[VEC_N];
__device__ int   g_cnt[2 * NSLOTS];
__device__ int2  g_list[2 * NSLOTS * LIST_CAP];
__device__ int   g_task[2];              // work-stealing counters (per layer)

// ---------------------------------------------------------------------------
__global__ void zero_cnt_kernel(int* __restrict__ cnt, int* __restrict__ task) {
    int i = blockIdx.x * blockDim.x + threadIdx.x;
    if (i < 2 * NSLOTS) cnt[i] = 0;
    if (i < 2) task[i] = 0;
}

// ---------------------------------------------------------------------------
// Compact both routing tensors in one launch.
// C layout [I,J,K,L]: q = ij*512 + k indexes a float4 over l.
// ---------------------------------------------------------------------------
__global__ void compact_kernel(const float4* __restrict__ C1,
                               const float4* __restrict__ C2,
                               int* __restrict__ cnt,
                               int2* __restrict__ lst) {
    const int n4 = C_ENTRIES / 4;           // per tensor
    int g = blockIdx.x * blockDim.x + threadIdx.x;
    int half = gridDim.x * blockDim.x / 2;
    const float4* C = (g < half) ? C1 : C2;
    int* cn  = (g < half) ? cnt : cnt + NSLOTS;
    int2* ls = (g < half) ? lst : lst + NSLOTS * LIST_CAP;
    int base = (g < half) ? g : g - half;
    int stride = half;
    for (int q = base; q < n4; q += stride) {
        float4 v = __ldcs(&C[q]);
        int ij = q >> 9;
        int k  = q & 511;
        float vals[4] = {v.x, v.y, v.z, v.w};
#pragma unroll
        for (int l = 0; l < 4; l++) {
            if (vals[l] != 0.0f) {
                int s = k * 4 + l;
                int pos = atomicAdd(&cn[s], 1);
                if (pos < LIST_CAP)
                    ls[s * LIST_CAP + pos] = make_int2(ij, __float_as_int(vals[l]));
            }
        }
    }
}

// ---------------------------------------------------------------------------
// Fused dispatch-gather + per-core matvec + capped ReLU, work-stealing tasks.
// Task = half core (128 rows). Per task: gather full 256-elem h into smem,
// then 8 warps x 16 rows. Row-group of 4 rows: lanes split (sub = lane>>3 ->
// row, lg = lane&7 -> 128B column chunk); 8 coalesced LDG.128 per row-group,
// 3-level shfl reduce within 8-lane groups.
// W per-core layout [j,k,l,m]: row r=(j,l) stride j:16384 l:64; col c=(k,m).
// ---------------------------------------------------------------------------
__global__ void __launch_bounds__(256) fused_mv_kernel(
        const float* __restrict__ W,
        const int*  __restrict__ cnt,
        const int2* __restrict__ lst,
        const float* __restrict__ src,
        float* __restrict__ y,
        int* __restrict__ task_ctr) {
    __shared__ float hs[PER_CORE];
    __shared__ int s_task;
    const int tid  = threadIdx.x;
    const int warp = tid >> 5, lane = tid & 31;
    const int lg  = lane & 7;    // column-chunk index
    const int sub = lane >> 3;   // row within group of 4

    for (;;) {
        if (tid == 0) s_task = atomicAdd(task_ctr, 1);
        __syncthreads();                    // publishes s_task, protects hs reuse
        const int task = s_task;
        if (task >= NTASKS) return;
        const int core = task >> 1;
        const int rbase = (task & 1) * 128; // which half of the rows

        // --- gather h for this core (256 threads <-> 256 elements) ---
        {
            int s = core * SLOTS + (tid >> 6);
            int m = tid & 63;
            int n = cnt[s];
            if (n > LIST_CAP) n = LIST_CAP;
            float acc = 0.0f;
#pragma unroll 4
            for (int e = 0; e < n; e++) {
                int2 ent = lst[s * LIST_CAP + e];
                acc += __int_as_float(ent.y) * src[ent.x * SLEN + m];
            }
            hs[tid] = acc;
        }
        __syncthreads();

        // Preload this lane's 8 h-chunks into registers
        float4 hv[8];
#pragma unroll
        for (int t = 0; t < 8; t++)
            hv[t] = reinterpret_cast<const float4*>(hs)[lg + 8 * t];

        const float* Wc = W + (size_t)core * (PER_CORE * PER_CORE);

#pragma unroll 2
        for (int rg = 0; rg < 4; rg++) {
            int r = rbase + warp * 16 + rg * 4 + sub;
            int j = r >> 6, l = r & 63;
            const float* rb = Wc + j * 16384 + l * 64;
            float acc = 0.0f;
#pragma unroll
            for (int t = 0; t < 8; t++) {
                int c = 4 * lg + 32 * t;
                float4 w = __ldcs(reinterpret_cast<const float4*>(
                                      rb + (c >> 6) * 4096 + (c & 63)));
                acc += w.x * hv[t].x + w.y * hv[t].y + w.z * hv[t].z + w.w * hv[t].w;
            }
            acc += __shfl_xor_sync(0xffffffffu, acc, 1);
            acc += __shfl_xor_sync(0xffffffffu, acc, 2);
            acc += __shfl_xor_sync(0xffffffffu, acc, 4);
            if (lg == 0)
                y[core * PER_CORE + r] = fminf(fmaxf(acc, 0.0f), 10.0f);
        }
    }
}

// ---------------------------------------------------------------------------
extern "C" void kernel_launch(void* const* d_in, const int* in_sizes, int n_in,
                              void* d_out, int out_size) {
    const float* x  = (const float*)d_in[0];
    const float* Wi = (const float*)d_in[1];
    const float* Wo = (const float*)d_in[2];
    const float* Ci = (const float*)d_in[3];
    const float* Cc = (const float*)d_in[4];
    float* out = (float*)d_out;

    float* y1;  cudaGetSymbolAddress((void**)&y1,  g_y1);
    int*   cnt; cudaGetSymbolAddress((void**)&cnt, g_cnt);
    int2*  lst; cudaGetSymbolAddress((void**)&lst, g_list);
    int*   tsk; cudaGetSymbolAddress((void**)&tsk, g_task);

    zero_cnt_kernel<<<(2 * NSLOTS + 255) / 256, 256>>>(cnt, tsk);

    compact_kernel<<<4096, 256>>>((const float4*)Ci, (const float4*)Cc,
                                  cnt, lst);

    // Layer 1: dispatch(x)+matvec(Wi) -> y1
    fused_mv_kernel<<<GRID_MV, 256>>>(Wi, cnt, lst, x, y1, tsk);

    // Layer 2: dispatch(y1)+matvec(Wo) -> out
    fused_mv_kernel<<<GRID_MV, 256>>>(Wo, cnt + NSLOTS,
                                      lst + NSLOTS * LIST_CAP, y1, out,
                                      tsk + 1);
}